// round 15
// baseline (speedup 1.0000x reference)
#include <cuda_runtime.h>
#include <math.h>

#define Hh 512
#define Ww 512
#define Bb 16
#define HW (Hh * Ww)
#define TOT (Bb * HW)
#define LOSS_BLOCKS_PER_B 8
#define NLOSSBLK (Bb * LOSS_BLOCKS_PER_B)

// ---------------- device scratch (static: no allocations allowed) ----------------
__device__ float         g_d[TOT];        // distance grid (pass1 out, then final)
__device__ float         g_w[TOT];        // boundary-loss weight w = t(1-p)+(1-t)p
__device__ unsigned char g_bmask[TOT];    // bit0: boundary, bit1: (tgt==0)
__device__ double        g_focal_acc;
__device__ double        g_inter[Bb], g_sp[Bb], g_st[Bb];
__device__ double        g_wsum[Bb], g_s2[Bb];
__device__ float         g_dmax[Bb];
__device__ int           g_hasb[Bb], g_hasfg[Bb];

// ---------------- zero accumulators (graph replay: reset every launch) ----------------
__global__ void zero_kernel() {
    int t = threadIdx.x;
    if (t == 0) g_focal_acc = 0.0;
    if (t < Bb) {
        g_inter[t] = 0.0; g_sp[t] = 0.0; g_st[t] = 0.0;
        g_wsum[t] = 0.0; g_s2[t] = 0.0;
        g_hasb[t] = 0; g_hasfg[t] = 0;
    }
}

// ---------------- boundary bits + per-sample flags ----------------
__global__ void prep_kernel(const int* __restrict__ tgt) {
    int idx = blockIdx.x * blockDim.x + threadIdx.x;   // grid sized exactly TOT
    int b   = idx / HW;
    int rem = idx - b * HW;
    int i   = rem / Ww;
    int j   = rem - i * Ww;
    const int* tb = tgt + b * HW;

    int anyFg = 0, anyBg = 0;
    #pragma unroll
    for (int di = -1; di <= 1; di++) {
        int ii = i + di;
        if (ii < 0 || ii >= Hh) continue;   // OOB contributes 0 to both maxpools
        #pragma unroll
        for (int dj = -1; dj <= 1; dj++) {
            int jj = j + dj;
            if (jj < 0 || jj >= Ww) continue;
            int v = tb[ii * Ww + jj];
            anyFg |= (v != 0);
            anyBg |= (v == 0);
        }
    }
    int boundary = anyFg & anyBg;            // dil==1 && ero==0
    int fgc      = (tb[rem] != 0);
    g_bmask[idx] = (unsigned char)(boundary | ((fgc ^ 1) << 1));

    int ab = __syncthreads_or(boundary);     // block lies fully inside one sample
    int af = __syncthreads_or(fgc);
    if (threadIdx.x == 0) {
        if (ab) atomicOr(&g_hasb[b], 1);
        if (af) atomicOr(&g_hasfg[b], 1);
    }
}

// ---------------- helpers ----------------
__device__ __forceinline__ float softplusf(float y) {
    return fmaxf(y, 0.0f) + log1pf(expf(-fabsf(y)));
}
__device__ __forceinline__ float warp_sum(float v) {
    for (int o = 16; o; o >>= 1) v += __shfl_down_sync(0xffffffffu, v, o);
    return v;
}

// Balanced tree min of 16 registers (depth 4): feeds the warp scan early.
__device__ __forceinline__ float tree_min16(const float* v) {
    float a0 = fminf(v[0], v[1]),  a1 = fminf(v[2], v[3]);
    float a2 = fminf(v[4], v[5]),  a3 = fminf(v[6], v[7]);
    float a4 = fminf(v[8], v[9]),  a5 = fminf(v[10], v[11]);
    float a6 = fminf(v[12], v[13]), a7 = fminf(v[14], v[15]);
    float b0 = fminf(a0, a1), b1 = fminf(a2, a3);
    float b2 = fminf(a4, a5), b3 = fminf(a6, a7);
    return fminf(fminf(b0, b1), fminf(b2, b3));
}

// Two-level inclusive min-scan over 16 registers (24 ops, depth ~28 cy).
#define LOCAL_CUMMIN16(v) do {                                                     \
    v[1]=fminf(v[1],v[0]);  v[5]=fminf(v[5],v[4]);                                 \
    v[9]=fminf(v[9],v[8]);  v[13]=fminf(v[13],v[12]);                              \
    v[2]=fminf(v[2],v[1]);  v[6]=fminf(v[6],v[5]);                                 \
    v[10]=fminf(v[10],v[9]); v[14]=fminf(v[14],v[13]);                             \
    v[3]=fminf(v[3],v[2]);  v[7]=fminf(v[7],v[6]);                                 \
    v[11]=fminf(v[11],v[10]); v[15]=fminf(v[15],v[14]);                            \
    v[7]=fminf(v[7],v[3]);  v[11]=fminf(v[11],v[7]);  v[15]=fminf(v[15],v[11]);    \
    v[4]=fminf(v[4],v[3]);  v[5]=fminf(v[5],v[3]);  v[6]=fminf(v[6],v[3]);         \
    v[8]=fminf(v[8],v[7]);  v[9]=fminf(v[9],v[7]);  v[10]=fminf(v[10],v[7]);       \
    v[12]=fminf(v[12],v[11]); v[13]=fminf(v[13],v[11]); v[14]=fminf(v[14],v[11]);  \
} while (0)

// Warp exclusive min-scan of per-lane group totals (gt). BIG identity at lane 0.
__device__ __forceinline__ float warp_excl_min(float gt, int t) {
    const unsigned full = 0xffffffffu;
    float incl = gt;
    #pragma unroll
    for (int off = 1; off < 32; off <<= 1) {
        float n = __shfl_up_sync(full, incl, off);
        if (t >= off) incl = fminf(incl, n);
    }
    float excl = __shfl_up_sync(full, incl, 1);
    if (t == 0) excl = 3.0e38f;
    return excl;
}

// ---------------- chamfer warp body: 1 warp per sample, 16 cols/thread ----------
// (round-10 structure, measured ~310us; pass-2 writeback quad order corrected)
__device__ void chamfer_body(int b, int t) {
    const float A = 0.955f, Bd = 1.3693f, INF = 1e6f;
    const unsigned full = 0xffffffffu;
    float* d = g_d + b * HW;
    const unsigned char* bm = g_bmask + b * HW;
    int hasb = g_hasb[b];

    float ajv[16];
    #pragma unroll
    for (int k = 0; k < 16; k++) ajv[k] = A * (float)(16 * t + k);

    float prev[16];
    #pragma unroll
    for (int k = 0; k < 16; k++) prev[k] = INF;
    float lh = INF, rh = INF;

    // ================= pass 1: top-left -> bottom-right =================
    // depth-2 prefetch: load row i+2 while computing row i (covers L2 ~262 cy)
    uint4 raw  = *(const uint4*)(bm + 0 * Ww + t * 16);
    uint4 rn1  = *(const uint4*)(bm + 1 * Ww + t * 16);
    for (int i = 0; i < Hh; i++) {
        uint4 rn2 = rn1;
        if (i + 2 < Hh) rn2 = *(const uint4*)(bm + (i + 2) * Ww + t * 16);

        // bit-plane select once per word: hasb uniform per sample; >>1 maps
        // bit1 of each byte onto bit0 of the same byte.
        unsigned ws0 = hasb ? raw.x : (raw.x >> 1);
        unsigned ws1 = hasb ? raw.y : (raw.y >> 1);
        unsigned ws2 = hasb ? raw.z : (raw.z >> 1);
        unsigned ws3 = hasb ? raw.w : (raw.w >> 1);

        float v[16];
        #pragma unroll
        for (int k = 0; k < 16; k++) {
            unsigned w  = (k < 4) ? ws0 : (k < 8) ? ws1 : (k < 12) ? ws2 : ws3;
            unsigned sel = (w >> (8 * (k & 3))) & 1u;
            float drow  = sel ? 0.0f : INF;
            float up = prev[k] + A;
            float ul = ((k > 0)  ? prev[k - 1] : lh) + Bd;
            float ur = ((k < 15) ? prev[k + 1] : rh) + Bd;
            float m  = fminf(fminf(drow, up), fminf(ul, ur));
            v[k] = m - ajv[k];
        }
        float gt = tree_min16(v);        // feeds warp scan at depth ~16
        float excl = warp_excl_min(gt, t);
        LOCAL_CUMMIN16(v);               // hidden under scan latency

        #pragma unroll
        for (int k = 0; k < 16; k++) prev[k] = ajv[k] + fminf(v[k], excl);

        // next-iteration halos issued before stores (overlap SHFL latency)
        lh = __shfl_up_sync(full, prev[15], 1);  if (t == 0)  lh = INF;
        rh = __shfl_down_sync(full, prev[0], 1); if (t == 31) rh = INF;

        float* row = d + i * Ww + t * 16;
        #pragma unroll
        for (int q = 0; q < 4; q++)
            *(float4*)(row + 4 * q) =
                make_float4(prev[4*q], prev[4*q+1], prev[4*q+2], prev[4*q+3]);
        raw = rn1; rn1 = rn2;
    }

    // ================= pass 2: on doubly-reversed grid =================
    // Thread t owns reversed cols j' in [16t,16t+16); original j = 511 - j'.
    #pragma unroll
    for (int k = 0; k < 16; k++) prev[k] = INF;
    lh = INF; rh = INF;
    float mx = 0.0f;
    int colbase = Ww - 16 - 16 * t;                     // orig col of chunk start

    float4 fc[4], f1[4];                                // depth-2 prefetch buffers
    {
        const float* r0 = d + (Hh - 1) * Ww + colbase;
        const float* r1 = d + (Hh - 2) * Ww + colbase;
        #pragma unroll
        for (int q = 0; q < 4; q++) { fc[q] = *(const float4*)(r0 + 4 * q);
                                      f1[q] = *(const float4*)(r1 + 4 * q); }
    }
    for (int ip = 0; ip < Hh; ip++) {
        int i = Hh - 1 - ip;
        float4 f2[4];
        #pragma unroll
        for (int q = 0; q < 4; q++) f2[q] = f1[q];
        if (i - 2 >= 0) {
            const float* row = d + (i - 2) * Ww + colbase;
            #pragma unroll
            for (int q = 0; q < 4; q++) f2[q] = *(const float4*)(row + 4 * q);
        }

        float dr[16];                                   // dr[k] = d[i][511-16t-k]
        #pragma unroll
        for (int q = 0; q < 4; q++) {
            dr[15 - 4*q - 0] = fc[q].x;
            dr[15 - 4*q - 1] = fc[q].y;
            dr[15 - 4*q - 2] = fc[q].z;
            dr[15 - 4*q - 3] = fc[q].w;
        }

        float v[16];
        #pragma unroll
        for (int k = 0; k < 16; k++) {
            float up = prev[k] + A;
            float ul = ((k > 0)  ? prev[k - 1] : lh) + Bd;
            float ur = ((k < 15) ? prev[k + 1] : rh) + Bd;
            float m  = fminf(fminf(dr[k], up), fminf(ul, ur));
            v[k] = m - ajv[k];
        }
        float gt = tree_min16(v);
        float excl = warp_excl_min(gt, t);
        LOCAL_CUMMIN16(v);

        #pragma unroll
        for (int k = 0; k < 16; k++) {
            float cur = ajv[k] + fminf(v[k], excl);
            prev[k] = cur;
            mx = fmaxf(mx, cur);
        }

        lh = __shfl_up_sync(full, prev[15], 1);  if (t == 0)  lh = INF;
        rh = __shfl_down_sync(full, prev[0], 1); if (t == 31) rh = INF;

        // orig col (colbase + 4q + e) holds local k = 15 - 4q - e
        float* row = d + i * Ww + colbase;
        #pragma unroll
        for (int q = 0; q < 4; q++)
            *(float4*)(row + 4 * q) =
                make_float4(prev[15-4*q], prev[15-4*q-1], prev[15-4*q-2], prev[15-4*q-3]);

        #pragma unroll
        for (int q = 0; q < 4; q++) { fc[q] = f1[q]; f1[q] = f2[q]; }
    }

    #pragma unroll
    for (int o = 16; o; o >>= 1) mx = fmaxf(mx, __shfl_down_sync(full, mx, o));
    if (t == 0) g_dmax[b] = mx;
}

// ---------------- dist-independent losses + w array (overlapped under chamfer) --
__device__ void loss_nodist_body(int lb, const float* __restrict__ pred,
                                 const int* __restrict__ tgt) {
    int b = lb / LOSS_BLOCKS_PER_B;
    int blk = lb - b * LOSS_BLOCKS_PER_B;
    const float* pb = pred + b * HW;
    const int*   tb = tgt  + b * HW;
    float*       wb = g_w  + b * HW;

    float fs = 0.f, is = 0.f, ps = 0.f, ts = 0.f, ws = 0.f;
    for (int base = blk * 1024 + threadIdx.x * 4; base < HW;
         base += LOSS_BLOCKS_PER_B * 1024) {
        float4 x4 = *(const float4*)(pb + base);
        int4   t4 = *(const int4*)(tb + base);
        float w4[4];
        #pragma unroll
        for (int e = 0; e < 4; e++) {
            float x = (e == 0) ? x4.x : (e == 1) ? x4.y : (e == 2) ? x4.z : x4.w;
            int  ti = (e == 0) ? t4.x : (e == 1) ? t4.y : (e == 2) ? t4.z : t4.w;
            float p  = 1.0f / (1.0f + expf(-x));
            float bce = ti ? softplusf(-x) : softplusf(x);  // -log_sigmoid(+-x)
            float w  = ti ? (1.0f - p) : p;                 // == 1 - pt
            float at = ti ? 0.25f : 0.75f;
            fs += at * w * w * bce;
            ws += w;
            if (ti) { is += p; ts += 1.0f; }
            ps += p;
            w4[e] = w;
        }
        *(float4*)(wb + base) = make_float4(w4[0], w4[1], w4[2], w4[3]);
    }

    __shared__ double acc[5];
    if (threadIdx.x < 5) acc[threadIdx.x] = 0.0;
    __syncthreads();
    fs = warp_sum(fs); is = warp_sum(is); ps = warp_sum(ps);
    ts = warp_sum(ts); ws = warp_sum(ws);
    if ((threadIdx.x & 31) == 0) {
        atomicAdd(&acc[0], (double)fs);
        atomicAdd(&acc[1], (double)is);
        atomicAdd(&acc[2], (double)ps);
        atomicAdd(&acc[3], (double)ts);
        atomicAdd(&acc[4], (double)ws);
    }
    __syncthreads();
    if (threadIdx.x == 0) {
        atomicAdd(&g_focal_acc, acc[0]);
        atomicAdd(&g_inter[b],  acc[1]);
        atomicAdd(&g_sp[b],     acc[2]);
        atomicAdd(&g_st[b],     acc[3]);
        atomicAdd(&g_wsum[b],   acc[4]);
    }
}

// ---------------- fused launch: 16 chamfer blocks + 128 loss blocks ------------
__global__ __launch_bounds__(256) void chamfer_loss_kernel(
        const float* __restrict__ pred, const int* __restrict__ tgt) {
    if (blockIdx.x < Bb) {
        if (threadIdx.x < 32) chamfer_body(blockIdx.x, threadIdx.x);
        return;                                 // no __syncthreads in this branch
    }
    loss_nodist_body(blockIdx.x - Bb, pred, tgt);
}

// ---------------- S2 = sum(w * d) per sample (bnd dist term) ----------------
__global__ void s2_kernel() {
    int b = blockIdx.y;
    const float* wb = g_w + b * HW;
    const float* db = g_d + b * HW;

    float s = 0.f;
    for (int base = blockIdx.x * 1024 + threadIdx.x * 4; base < HW;
         base += gridDim.x * 1024) {
        float4 w4 = *(const float4*)(wb + base);
        float4 d4 = *(const float4*)(db + base);
        s += w4.x * d4.x + w4.y * d4.y + w4.z * d4.z + w4.w * d4.w;
    }

    __shared__ double acc;
    if (threadIdx.x == 0) acc = 0.0;
    __syncthreads();
    s = warp_sum(s);
    if ((threadIdx.x & 31) == 0) atomicAdd(&acc, (double)s);
    __syncthreads();
    if (threadIdx.x == 0) atomicAdd(&g_s2[b], acc);
}

// ---------------- finalize: dice/iou ratios + bnd assembly + weighting ----------
__global__ void final_kernel(const float* __restrict__ lv, float* __restrict__ out) {
    if (threadIdx.x != 0 || blockIdx.x != 0) return;
    double N = (double)TOT;
    double focal = g_focal_acc / N;
    double bnd_sum = 0.0, dsum = 0.0, isum = 0.0;
    for (int b = 0; b < Bb; b++) {
        double inter = g_inter[b];
        double tot   = g_sp[b] + g_st[b];
        dsum += (2.0 * inter + 1e-6) / (tot + 1e-6);
        isum += (inter + 1e-6) / (tot - inter + 1e-6);
        double S1 = g_wsum[b], S2 = g_s2[b];
        if (!g_hasfg[b]) {
            bnd_sum += 2.0 * S1;                 // dist == 1 everywhere
        } else {
            double dmax = (double)g_dmax[b];
            bnd_sum += S1 + (dmax > 0.0 ? S2 / fmax(dmax, 1e-12) : S2);
        }
    }
    double bnd  = bnd_sum / N;
    double dice = 1.0 - dsum / (double)Bb;
    double iou  = 1.0 - isum / (double)Bb;
    double l0 = lv[0], l1 = lv[1], l2 = lv[2], l3 = lv[3];
    double total = exp(-l0) * focal + l0
                 + exp(-l1) * dice  + l1
                 + exp(-l2) * bnd   + l2
                 + exp(-l3) * iou   + l3;
    out[0] = (float)total;
    out[1] = (float)focal;
    out[2] = (float)dice;
    out[3] = (float)bnd;
    out[4] = (float)iou;
}

extern "C" void kernel_launch(void* const* d_in, const int* in_sizes, int n_in,
                              void* d_out, int out_size) {
    const float* pred = (const float*)d_in[0];
    const int*   tgt  = (const int*)d_in[1];
    const float* lv   = (const float*)d_in[2];
    float* out = (float*)d_out;
    (void)in_sizes; (void)n_in; (void)out_size;

    zero_kernel<<<1, 64>>>();
    prep_kernel<<<TOT / 256, 256>>>(tgt);
    chamfer_loss_kernel<<<Bb + NLOSSBLK, 256>>>(pred, tgt);
    s2_kernel<<<dim3(32, Bb), 256>>>();
    final_kernel<<<1, 32>>>(lv, out);
}